// round 1
// baseline (speedup 1.0000x reference)
#include <cuda_runtime.h>
#include <cuda_bf16.h>
#include <cub/cub.cuh>
#include <cstdint>

// Problem constants
constexpr int Bq = 2, Eq = 16, Hq = 160, Wq = 288, Nq = 12, Tq = 2;
constexpr int HW  = Hq * Wq;            // 46080
constexpr int P   = Tq * HW;            // 92160 pixels per instance
constexpr int BN  = Bq * Nq;            // 24 instances
constexpr int TOT = BN * P;             // 2211840 total elements
constexpr int SCH = 45;                 // stat chunks per instance
constexpr int PIX_PER_CHUNK = P / SCH;  // 2048
constexpr int LOSS_THREADS = 512;
constexpr int LOSS_ITEMS   = 4;
constexpr int LOSS_CHUNK   = LOSS_THREADS * LOSS_ITEMS;   // 2048
constexpr int LOSS_NCHUNK  = P / LOSS_CHUNK;              // 45

// -------- scratch (static device globals; no runtime allocation) --------
__device__ float g_emb[(size_t)Bq * Tq * HW * Eq];   // (b,t,hw,e) e-contiguous, 11.8MB
__device__ float g_part[BN * SCH * 33];
__device__ float g_mean[BN * Eq];
__device__ float g_var[BN * Eq];
__device__ float g_cnt[BN];
__device__ unsigned long long g_keys_in[TOT];        // 17.7MB
__device__ unsigned long long g_keys_out[TOT];       // 17.7MB
__device__ float g_loss[BN];
__device__ unsigned char g_sort_temp[64u << 20];     // 64MB CUB temp

// -------- kernel 1: transpose feats (B,E,H,W)x2 -> (b,t,hw,e) --------
__global__ void k_transpose(const float* __restrict__ f1, const float* __restrict__ f2) {
    int idx = blockIdx.x * blockDim.x + threadIdx.x;   // over B*T*HW
    if (idx >= Bq * Tq * HW) return;
    int hw = idx % HW;
    int bt = idx / HW;
    int t  = bt % Tq;
    int b  = bt / Tq;
    const float* src = (t == 0 ? f1 : f2) + (size_t)b * Eq * HW + hw;
    float v[Eq];
#pragma unroll
    for (int e = 0; e < Eq; e++) v[e] = src[(size_t)e * HW];
    float4* dst = reinterpret_cast<float4*>(&g_emb[(size_t)idx * Eq]);
#pragma unroll
    for (int j = 0; j < 4; j++)
        dst[j] = make_float4(v[4 * j], v[4 * j + 1], v[4 * j + 2], v[4 * j + 3]);
}

// -------- kernel 2: per-instance partial sums (sum, sumsq, count) --------
__global__ void k_stats(const int* __restrict__ gt) {
    int bn = blockIdx.x / SCH;
    int ch = blockIdx.x % SCH;
    int b  = bn / Nq;
    int base = ch * PIX_PER_CHUNK;

    float a[33];
#pragma unroll
    for (int q = 0; q < 33; q++) a[q] = 0.f;

    for (int i = threadIdx.x; i < PIX_PER_CHUNK; i += blockDim.x) {
        int p = base + i;
        float m = (float)gt[(size_t)bn * P + p];
        const float4* e4 = reinterpret_cast<const float4*>(&g_emb[((size_t)b * P + p) * Eq]);
        a[32] += m;
#pragma unroll
        for (int j = 0; j < 4; j++) {
            float4 v = e4[j];
            a[4 * j + 0] += m * v.x;  a[16 + 4 * j + 0] += m * v.x * v.x;
            a[4 * j + 1] += m * v.y;  a[16 + 4 * j + 1] += m * v.y * v.y;
            a[4 * j + 2] += m * v.z;  a[16 + 4 * j + 2] += m * v.z * v.z;
            a[4 * j + 3] += m * v.w;  a[16 + 4 * j + 3] += m * v.w * v.w;
        }
    }

    // warp shuffle reduce each of 33 quantities
#pragma unroll
    for (int q = 0; q < 33; q++)
#pragma unroll
        for (int off = 16; off > 0; off >>= 1)
            a[q] += __shfl_down_sync(0xFFFFFFFFu, a[q], off);

    __shared__ float ws[8][33];
    int warp = threadIdx.x >> 5, lane = threadIdx.x & 31;
    if (lane == 0)
#pragma unroll
        for (int q = 0; q < 33; q++) ws[warp][q] = a[q];
    __syncthreads();

    int nw = blockDim.x >> 5;
    if (threadIdx.x < 33) {
        float s = 0.f;
        for (int w = 0; w < nw; w++) s += ws[w][threadIdx.x];
        g_part[((size_t)bn * SCH + ch) * 33 + threadIdx.x] = s;
    }
}

// -------- kernel 3: finalize mean / var / cnt --------
__global__ void k_stats2() {
    int bn = blockIdx.x;
    int q  = threadIdx.x;
    __shared__ float sums[33];
    if (q < 33) {
        float s = 0.f;
        for (int ch = 0; ch < SCH; ch++) s += g_part[((size_t)bn * SCH + ch) * 33 + q];
        sums[q] = s;
    }
    __syncthreads();
    if (q < Eq) {
        float cnt  = sums[32];
        float mean = sums[q] / cnt;
        float var  = (sums[16 + q] - cnt * mean * mean) / (cnt - 1.0f);
        g_mean[bn * Eq + q] = mean;
        g_var[bn * Eq + q]  = var;
        if (q == 0) g_cnt[bn] = cnt;
    }
}

// -------- kernel 4: per-pixel error -> 64-bit sort key --------
// key = (bn << 32) | ~float_bits(err), label in error LSB. Ascending u64 sort
// => segments ordered by bn, errors descending within segment.
__global__ void k_errors(const int* __restrict__ gt) {
    __shared__ float sm[Eq], sv[Eq];
    int bn = (int)(((size_t)blockIdx.x * blockDim.x) / P);  // P % blockDim == 0
    if (threadIdx.x < Eq) {
        sm[threadIdx.x] = g_mean[bn * Eq + threadIdx.x];
        sv[threadIdx.x] = g_var[bn * Eq + threadIdx.x];
    }
    __syncthreads();

    size_t idx = (size_t)blockIdx.x * blockDim.x + threadIdx.x;
    if (idx >= (size_t)TOT) return;
    int p = (int)(idx % P);
    int b = bn / Nq;

    int m = gt[idx];
    const float4* e4 = reinterpret_cast<const float4*>(&g_emb[((size_t)b * P + p) * Eq]);
    float d = 0.f;
#pragma unroll
    for (int j = 0; j < 4; j++) {
        float4 v = e4[j];
        float dx = v.x - sm[4 * j + 0];
        float dy = v.y - sm[4 * j + 1];
        float dz = v.z - sm[4 * j + 2];
        float dw = v.w - sm[4 * j + 3];
        d += dx * dx * sv[4 * j + 0] + dy * dy * sv[4 * j + 1]
           + dz * dz * sv[4 * j + 2] + dw * dw * sv[4 * j + 3];
    }
    float logit = 2.0f * __expf(-0.5f * d) - 1.0f;
    float sign  = m ? 1.0f : -1.0f;
    float err   = 1.0f - sign * logit;          // always >= 0
    unsigned int bits = __float_as_uint(err);
    bits = (bits & ~1u) | (unsigned int)m;      // embed label in mantissa LSB
    g_keys_in[idx] = ((unsigned long long)bn << 32) | (unsigned long long)(~bits);
}

// -------- kernel 5: Lovász scan + dot per instance --------
__global__ void k_loss() {
    int bn = blockIdx.x;
    float gts = g_cnt[bn];

    typedef cub::BlockScan<int, LOSS_THREADS> Scan;
    __shared__ typename Scan::TempStorage ts;

    float loss = 0.f;
    int carry = 0;

    for (int ch = 0; ch < LOSS_NCHUNK; ch++) {
        int pos0 = ch * LOSS_CHUNK + threadIdx.x * LOSS_ITEMS;    // position of item 0
        size_t base = (size_t)bn * P + pos0;
        const ulonglong2* src = reinterpret_cast<const ulonglong2*>(&g_keys_out[base]);
        ulonglong2 k01 = src[0];
        ulonglong2 k23 = src[1];
        unsigned int eb[LOSS_ITEMS];
        int g[LOSS_ITEMS];
        eb[0] = ~(unsigned int)k01.x;  eb[1] = ~(unsigned int)k01.y;
        eb[2] = ~(unsigned int)k23.x;  eb[3] = ~(unsigned int)k23.y;
#pragma unroll
        for (int i = 0; i < LOSS_ITEMS; i++) g[i] = (int)(eb[i] & 1u);

        int tsum = g[0] + g[1] + g[2] + g[3];
        int excl, agg;
        Scan(ts).ExclusiveSum(tsum, excl, agg);

        int c = carry + excl;
#pragma unroll
        for (int i = 0; i < LOSS_ITEMS; i++) {
            c += g[i];
            float k1  = (float)(pos0 + i + 1);
            float err = __uint_as_float(eb[i]);
            float cf  = (float)c;
            float cpf = (float)(c - g[i]);
            // J(c,k) = 1 - (gts-c)/(gts+k-c);  J(0,0) = 0 via formula (gts>0)
            float J   = 1.0f - (gts - cf)  / (gts + k1 - cf);
            float Jp  = 1.0f - (gts - cpf) / (gts + (k1 - 1.0f) - cpf);
            loss += err * (J - Jp);
        }
        carry += agg;
        __syncthreads();   // temp storage reuse
    }

    // block reduce loss (deterministic tree)
    __shared__ float red[LOSS_THREADS];
    red[threadIdx.x] = loss;
    __syncthreads();
    for (int s = LOSS_THREADS / 2; s > 0; s >>= 1) {
        if (threadIdx.x < s) red[threadIdx.x] += red[threadIdx.x + s];
        __syncthreads();
    }
    if (threadIdx.x == 0) g_loss[bn] = red[0];
}

// -------- kernel 6: final deterministic average --------
__global__ void k_final(float* __restrict__ out) {
    if (threadIdx.x == 0) {
        float s = 0.f;
        for (int i = 0; i < BN; i++) s += g_loss[i];
        out[0] = s / (float)BN;
    }
}

extern "C" void kernel_launch(void* const* d_in, const int* in_sizes, int n_in,
                              void* d_out, int out_size) {
    const float* f1 = (const float*)d_in[0];
    const float* f2 = (const float*)d_in[1];
    const int*   gt = (const int*)d_in[2];
    float* out = (float*)d_out;

    k_transpose<<<(Bq * Tq * HW + 255) / 256, 256>>>(f1, f2);
    k_stats<<<BN * SCH, 256>>>(gt);
    k_stats2<<<BN, 64>>>();
    k_errors<<<TOT / 256, 256>>>(gt);   // TOT divisible by 256

    void *d_tmp = nullptr, *d_kin = nullptr, *d_kout = nullptr;
    cudaGetSymbolAddress(&d_tmp, g_sort_temp);
    cudaGetSymbolAddress(&d_kin, g_keys_in);
    cudaGetSymbolAddress(&d_kout, g_keys_out);

    size_t temp_bytes = 0;
    cub::DeviceRadixSort::SortKeys(nullptr, temp_bytes,
                                   (const unsigned long long*)d_kin,
                                   (unsigned long long*)d_kout,
                                   TOT, 0, 37);
    if (temp_bytes <= sizeof(g_sort_temp)) {
        cub::DeviceRadixSort::SortKeys(d_tmp, temp_bytes,
                                       (const unsigned long long*)d_kin,
                                       (unsigned long long*)d_kout,
                                       TOT, 0, 37);
    }

    k_loss<<<BN, LOSS_THREADS>>>();
    k_final<<<1, 32>>>(out);
}

// round 3
// speedup vs baseline: 3.3137x; 3.3137x over previous
#include <cuda_runtime.h>
#include <cuda_bf16.h>
#include <cub/cub.cuh>
#include <cstdint>

// Problem constants
constexpr int Bq = 2, Eq = 16, Hq = 160, Wq = 288, Nq = 12, Tq = 2;
constexpr int HW  = Hq * Wq;            // 46080
constexpr int P   = Tq * HW;            // 92160 pixels per instance
constexpr int BN  = Bq * Nq;            // 24 instances
constexpr int SCH = 45;                 // stat chunks per instance
constexpr int PIX_PER_CHUNK = P / SCH;  // 2048

constexpr int NB = 16384;               // histogram bins over err in [0,2]
constexpr int ECH = 6;                  // err/hist chunks per instance
constexpr int EPIX = P / ECH;           // 15360 px per err block
constexpr int ETHREADS = 512;
constexpr float FXS = 16384.0f;         // fixed-point scale 2^14

constexpr int LTHREADS = 256;
constexpr int LITEMS = 8;               // bins per thread per iter
constexpr int LCHUNK = LTHREADS * LITEMS;   // 2048
constexpr int LNITER = NB / LCHUNK;         // 8

// -------- scratch (static device globals; no runtime allocation) --------
__device__ float g_part[BN * SCH * 33];
__device__ float g_mean[BN * Eq];
__device__ float g_var[BN * Eq];
__device__ float g_cnt[BN];
__device__ unsigned int g_hist_pos[BN * NB];
__device__ unsigned int g_hist_neg[BN * NB];
__device__ unsigned long long g_hist_sum[BN * NB];   // err * 2^14 fixed point
__device__ float g_loss[BN];

// -------- kernel 1: per-instance partial sums (sum, sumsq, count) --------
__global__ void k_stats(const float* __restrict__ f1, const float* __restrict__ f2,
                        const int* __restrict__ gt) {
    int bn = blockIdx.x / SCH;
    int ch = blockIdx.x % SCH;
    int b  = bn / Nq;
    int base = ch * PIX_PER_CHUNK;

    float a[33];
#pragma unroll
    for (int q = 0; q < 33; q++) a[q] = 0.f;

    for (int i = threadIdx.x; i < PIX_PER_CHUNK; i += blockDim.x) {
        int p = base + i;
        int t = (p >= HW) ? 1 : 0;
        int hw = p - t * HW;
        const float* fb = (t ? f2 : f1) + (size_t)b * Eq * HW + hw;
        float m = (float)gt[(size_t)bn * P + p];
        a[32] += m;
#pragma unroll
        for (int e = 0; e < Eq; e++) {
            float v = fb[(size_t)e * HW];
            a[e]      += m * v;
            a[16 + e] += m * v * v;
        }
    }

#pragma unroll
    for (int q = 0; q < 33; q++)
#pragma unroll
        for (int off = 16; off > 0; off >>= 1)
            a[q] += __shfl_down_sync(0xFFFFFFFFu, a[q], off);

    __shared__ float ws[8][33];
    int warp = threadIdx.x >> 5, lane = threadIdx.x & 31;
    if (lane == 0)
#pragma unroll
        for (int q = 0; q < 33; q++) ws[warp][q] = a[q];
    __syncthreads();

    int nw = blockDim.x >> 5;
    if (threadIdx.x < 33) {
        float s = 0.f;
        for (int w = 0; w < nw; w++) s += ws[w][threadIdx.x];
        g_part[((size_t)bn * SCH + ch) * 33 + threadIdx.x] = s;
    }
}

// -------- kernel 2: finalize mean / var / cnt --------
__global__ void k_stats2() {
    int bn = blockIdx.x;
    int q  = threadIdx.x;
    __shared__ float sums[33];
    if (q < 33) {
        float s = 0.f;
        for (int ch = 0; ch < SCH; ch++) s += g_part[((size_t)bn * SCH + ch) * 33 + q];
        sums[q] = s;
    }
    __syncthreads();
    if (q < Eq) {
        float cnt  = sums[32];
        float mean = sums[q] / cnt;
        float var  = (sums[16 + q] - cnt * mean * mean) / (cnt - 1.0f);
        g_mean[bn * Eq + q] = mean;
        g_var[bn * Eq + q]  = var;
        if (q == 0) g_cnt[bn] = cnt;
    }
}

// -------- kernel 3: per-pixel error -> per-instance histogram --------
// smem layout (dynamic): u32 hsum[NB] (64KB, err*2^14) then u32 hcnt[NB] (64KB,
// pos<<16|neg). Total 128KB.
__global__ void k_errhist(const float* __restrict__ f1, const float* __restrict__ f2,
                          const int* __restrict__ gt) {
    extern __shared__ unsigned char sh[];
    unsigned int* hsum = (unsigned int*)sh;
    unsigned int* hcnt = (unsigned int*)(sh + (size_t)NB * 4);
    __shared__ float sm[Eq], sv[Eq];

    int bn = blockIdx.x / ECH;
    int ch = blockIdx.x % ECH;
    int b  = bn / Nq;
    int base = ch * EPIX;

    for (int i = threadIdx.x; i < NB; i += ETHREADS) { hsum[i] = 0u; hcnt[i] = 0u; }
    if (threadIdx.x < Eq) {
        sm[threadIdx.x] = g_mean[bn * Eq + threadIdx.x];
        sv[threadIdx.x] = g_var[bn * Eq + threadIdx.x];
    }
    __syncthreads();

    // register accumulators for the (hot) edge bins 0 and NB-1
    unsigned int c0 = 0, cM = 0;               // packed pos<<16|neg
    unsigned long long s0 = 0ull, sM = 0ull;

    for (int i = threadIdx.x; i < EPIX; i += ETHREADS) {
        int p = base + i;
        int t = (p >= HW) ? 1 : 0;
        int hw = p - t * HW;
        const float* fb = (t ? f2 : f1) + (size_t)b * Eq * HW + hw;
        int m = gt[(size_t)bn * P + p];

        float d = 0.f;
#pragma unroll
        for (int e = 0; e < Eq; e++) {
            float dv = fb[(size_t)e * HW] - sm[e];
            d += dv * dv * sv[e];
        }
        float logit = 2.0f * __expf(-0.5f * d) - 1.0f;
        float sign  = m ? 1.0f : -1.0f;
        float err   = 1.0f - sign * logit;           // in [0,2]

        unsigned int fx = (unsigned int)(err * FXS);
        int bin = (int)(err * (0.5f * NB));
        if (bin > NB - 1) bin = NB - 1;
        unsigned int pc = m ? 0x10000u : 1u;

        if (bin == 0)           { c0 += pc; s0 += fx; }
        else if (bin == NB - 1) { cM += pc; sM += fx; }
        else {
            atomicAdd(&hcnt[bin], pc);
            atomicAdd(&hsum[bin], fx);
        }
    }
    __syncthreads();

    // merge block-local histogram into global per-instance histogram
    size_t gbase = (size_t)bn * NB;
    for (int i = threadIdx.x; i < NB; i += ETHREADS) {
        unsigned int c = hcnt[i];
        if (c) {
            atomicAdd(&g_hist_pos[gbase + i], c >> 16);
            atomicAdd(&g_hist_neg[gbase + i], c & 0xFFFFu);
            atomicAdd(&g_hist_sum[gbase + i], (unsigned long long)hsum[i]);
        }
    }
    // flush edge register accumulators straight to global (u64, no overflow)
    // reduce within warp first to cut atomic count 32x
#pragma unroll
    for (int off = 16; off > 0; off >>= 1) {
        c0 += __shfl_down_sync(0xFFFFFFFFu, c0, off);
        cM += __shfl_down_sync(0xFFFFFFFFu, cM, off);
        s0 += __shfl_down_sync(0xFFFFFFFFu, s0, off);
        sM += __shfl_down_sync(0xFFFFFFFFu, sM, off);
    }
    if ((threadIdx.x & 31) == 0) {
        if (c0) {
            atomicAdd(&g_hist_pos[gbase + 0], c0 >> 16);
            atomicAdd(&g_hist_neg[gbase + 0], c0 & 0xFFFFu);
            atomicAdd(&g_hist_sum[gbase + 0], s0);
        }
        if (cM) {
            atomicAdd(&g_hist_pos[gbase + NB - 1], cM >> 16);
            atomicAdd(&g_hist_neg[gbase + NB - 1], cM & 0xFFFFu);
            atomicAdd(&g_hist_sum[gbase + NB - 1], sM);
        }
    }
}

// -------- kernel 4: Lovász via descending-bin scan --------
// loss = sum over bins (desc err): mean_err_bin * (J(c_end,k_end) - J(c_start,k_start))
// J(c,k) = 1 - (gts-c)/(gts+k-c); exact group telescoping of the jaccard deltas.
__global__ void k_losshist() {
    int bn = blockIdx.x;
    float gts = g_cnt[bn];
    size_t gbase = (size_t)bn * NB;

    typedef cub::BlockScan<unsigned long long, LTHREADS> Scan;
    __shared__ typename Scan::TempStorage ts;

    float loss = 0.f;
    unsigned long long carry = 0ull;   // (c << 32) | k

    for (int it = 0; it < LNITER; it++) {
        int v0 = it * LCHUNK + threadIdx.x * LITEMS;
        unsigned int cp[LITEMS], tot[LITEMS];
        unsigned long long fx[LITEMS];
        unsigned long long tsum = 0ull;
#pragma unroll
        for (int i = 0; i < LITEMS; i++) {
            int bin = NB - 1 - (v0 + i);
            unsigned int p = g_hist_pos[gbase + bin];
            unsigned int n = g_hist_neg[gbase + bin];
            cp[i] = p; tot[i] = p + n;
            fx[i] = g_hist_sum[gbase + bin];
            tsum += ((unsigned long long)p << 32) | (unsigned long long)(p + n);
        }

        unsigned long long excl, agg;
        Scan(ts).ExclusiveSum(tsum, excl, agg);

        unsigned long long run = carry + excl;
#pragma unroll
        for (int i = 0; i < LITEMS; i++) {
            if (tot[i]) {
                float cA = (float)(unsigned int)(run >> 32);
                float kA = (float)(unsigned int)(run & 0xFFFFFFFFull);
                float cBv = cA + (float)cp[i];
                float kBv = kA + (float)tot[i];
                float JA = 1.0f - (gts - cA)  / (gts + kA  - cA);
                float JB = 1.0f - (gts - cBv) / (gts + kBv - cBv);
                float err_rep = (float)fx[i] / (FXS * (float)tot[i]);
                loss += err_rep * (JB - JA);
            }
            run += ((unsigned long long)cp[i] << 32) | (unsigned long long)tot[i];
        }
        carry += agg;
        __syncthreads();
    }

    __shared__ float red[LTHREADS];
    red[threadIdx.x] = loss;
    __syncthreads();
    for (int s = LTHREADS / 2; s > 0; s >>= 1) {
        if (threadIdx.x < s) red[threadIdx.x] += red[threadIdx.x + s];
        __syncthreads();
    }
    if (threadIdx.x == 0) g_loss[bn] = red[0];
}

// -------- kernel 5: final deterministic average --------
__global__ void k_final(float* __restrict__ out) {
    if (threadIdx.x == 0) {
        float s = 0.f;
        for (int i = 0; i < BN; i++) s += g_loss[i];
        out[0] = s / (float)BN;
    }
}

extern "C" void kernel_launch(void* const* d_in, const int* in_sizes, int n_in,
                              void* d_out, int out_size) {
    const float* f1 = (const float*)d_in[0];
    const float* f2 = (const float*)d_in[1];
    const int*   gt = (const int*)d_in[2];
    float* out = (float*)d_out;

    // zero global histograms
    void *hp = nullptr, *hn = nullptr, *hs = nullptr;
    cudaGetSymbolAddress(&hp, g_hist_pos);
    cudaGetSymbolAddress(&hn, g_hist_neg);
    cudaGetSymbolAddress(&hs, g_hist_sum);
    cudaMemsetAsync(hp, 0, sizeof(unsigned int) * BN * NB);
    cudaMemsetAsync(hn, 0, sizeof(unsigned int) * BN * NB);
    cudaMemsetAsync(hs, 0, sizeof(unsigned long long) * BN * NB);

    k_stats<<<BN * SCH, 256>>>(f1, f2, gt);
    k_stats2<<<BN, 64>>>();

    constexpr size_t ESMEM = (size_t)NB * 4 * 2;  // 131072 B
    cudaFuncSetAttribute(k_errhist, cudaFuncAttributeMaxDynamicSharedMemorySize,
                         (int)ESMEM);
    k_errhist<<<BN * ECH, ETHREADS, ESMEM>>>(f1, f2, gt);

    k_losshist<<<BN, LTHREADS>>>();
    k_final<<<1, 32>>>(out);
}

// round 4
// speedup vs baseline: 4.0678x; 1.2276x over previous
#include <cuda_runtime.h>
#include <cuda_bf16.h>
#include <cub/cub.cuh>
#include <cstdint>

// Problem constants
constexpr int Bq = 2, Eq = 16, Hq = 160, Wq = 288, Nq = 12, Tq = 2;
constexpr int HW  = Hq * Wq;            // 46080
constexpr int P   = Tq * HW;            // 92160 pixels per instance
constexpr int BN  = Bq * Nq;            // 24 instances
constexpr int SCH = 45;                 // stat chunks per instance
constexpr int PIX_PER_CHUNK = P / SCH;  // 2048

constexpr int NB = 16384;               // histogram bins over err in [0,2]
constexpr int ECH = 6;                  // err/hist chunks per instance
constexpr int EPIX = P / ECH;           // 15360 px per err block
constexpr int ETHREADS = 512;
constexpr float FXS = 16384.0f;         // fixed-point scale 2^14

constexpr int LCH = 8;                  // loss chunks per instance
constexpr int LBINS = NB / LCH;         // 2048 bins per loss block
constexpr int LTHREADS = 256;
constexpr int LITEMS = LBINS / LTHREADS;   // 8

// -------- scratch (static device globals; no runtime allocation) --------
__device__ float g_part[BN * SCH * 33];
__device__ float g_mean[BN * Eq];
__device__ float g_var[BN * Eq];
__device__ float g_cnt[BN];
__device__ unsigned int g_hist_pos[BN * NB];
__device__ unsigned int g_hist_neg[BN * NB];
__device__ unsigned int g_hist_sum[BN * NB];   // err * 2^14 fixed point (u32: max 3.0e9)
__device__ float g_losspart[BN * LCH];

// -------- kernel 1: per-instance partial sums (sum, sumsq, count) --------
__global__ void k_stats(const float* __restrict__ f1, const float* __restrict__ f2,
                        const int* __restrict__ gt) {
    int bn = blockIdx.x / SCH;
    int ch = blockIdx.x % SCH;
    int b  = bn / Nq;
    int base = ch * PIX_PER_CHUNK;

    float a[33];
#pragma unroll
    for (int q = 0; q < 33; q++) a[q] = 0.f;

    for (int i = threadIdx.x; i < PIX_PER_CHUNK; i += blockDim.x) {
        int p = base + i;
        int t = (p >= HW) ? 1 : 0;
        int hw = p - t * HW;
        const float* fb = (t ? f2 : f1) + (size_t)b * Eq * HW + hw;
        float m = (float)gt[(size_t)bn * P + p];
        a[32] += m;
#pragma unroll
        for (int e = 0; e < Eq; e++) {
            float v = fb[(size_t)e * HW];
            a[e]      += m * v;
            a[16 + e] += m * v * v;
        }
    }

#pragma unroll
    for (int q = 0; q < 33; q++)
#pragma unroll
        for (int off = 16; off > 0; off >>= 1)
            a[q] += __shfl_down_sync(0xFFFFFFFFu, a[q], off);

    __shared__ float ws[8][33];
    int warp = threadIdx.x >> 5, lane = threadIdx.x & 31;
    if (lane == 0)
#pragma unroll
        for (int q = 0; q < 33; q++) ws[warp][q] = a[q];
    __syncthreads();

    int nw = blockDim.x >> 5;
    if (threadIdx.x < 33) {
        float s = 0.f;
        for (int w = 0; w < nw; w++) s += ws[w][threadIdx.x];
        g_part[((size_t)bn * SCH + ch) * 33 + threadIdx.x] = s;
    }
}

// -------- kernel 2: finalize mean / var / cnt --------
__global__ void k_stats2() {
    int bn = blockIdx.x;
    int q  = threadIdx.x;
    __shared__ float sums[33];
    if (q < 33) {
        float s = 0.f;
        for (int ch = 0; ch < SCH; ch++) s += g_part[((size_t)bn * SCH + ch) * 33 + q];
        sums[q] = s;
    }
    __syncthreads();
    if (q < Eq) {
        float cnt  = sums[32];
        float mean = sums[q] / cnt;
        float var  = (sums[16 + q] - cnt * mean * mean) / (cnt - 1.0f);
        g_mean[bn * Eq + q] = mean;
        g_var[bn * Eq + q]  = var;
        if (q == 0) g_cnt[bn] = cnt;
    }
}

// -------- kernel 3: per-pixel error -> per-instance histogram --------
// smem layout (dynamic): u32 hsum[NB] (64KB, err*2^14) then u32 hcnt[NB] (64KB,
// pos<<16|neg). Total 128KB.
__global__ void k_errhist(const float* __restrict__ f1, const float* __restrict__ f2,
                          const int* __restrict__ gt) {
    extern __shared__ unsigned char sh[];
    unsigned int* hsum = (unsigned int*)sh;
    unsigned int* hcnt = (unsigned int*)(sh + (size_t)NB * 4);
    __shared__ float sm[Eq], sv[Eq];

    int bn = blockIdx.x / ECH;
    int ch = blockIdx.x % ECH;
    int b  = bn / Nq;
    int base = ch * EPIX;

    for (int i = threadIdx.x; i < NB; i += ETHREADS) { hsum[i] = 0u; hcnt[i] = 0u; }
    if (threadIdx.x < Eq) {
        sm[threadIdx.x] = g_mean[bn * Eq + threadIdx.x];
        sv[threadIdx.x] = g_var[bn * Eq + threadIdx.x];
    }
    __syncthreads();

    // register accumulators for the (hot) edge bins 0 and NB-1
    unsigned int c0 = 0, cM = 0;               // packed pos<<16|neg
    unsigned long long s0 = 0ull, sM = 0ull;

    for (int i = threadIdx.x; i < EPIX; i += ETHREADS) {
        int p = base + i;
        int t = (p >= HW) ? 1 : 0;
        int hw = p - t * HW;
        const float* fb = (t ? f2 : f1) + (size_t)b * Eq * HW + hw;
        int m = gt[(size_t)bn * P + p];

        float d = 0.f;
#pragma unroll
        for (int e = 0; e < Eq; e++) {
            float dv = fb[(size_t)e * HW] - sm[e];
            d += dv * dv * sv[e];
        }
        float logit = 2.0f * __expf(-0.5f * d) - 1.0f;
        float sign  = m ? 1.0f : -1.0f;
        float err   = 1.0f - sign * logit;           // in [0,2]

        unsigned int fx = (unsigned int)(err * FXS);
        int bin = (int)(err * (0.5f * NB));
        if (bin > NB - 1) bin = NB - 1;
        unsigned int pc = m ? 0x10000u : 1u;

        if (bin == 0)           { c0 += pc; s0 += fx; }
        else if (bin == NB - 1) { cM += pc; sM += fx; }
        else {
            atomicAdd(&hcnt[bin], pc);
            atomicAdd(&hsum[bin], fx);
        }
    }
    __syncthreads();

    // merge block-local histogram into global per-instance histogram
    size_t gbase = (size_t)bn * NB;
    for (int i = threadIdx.x; i < NB; i += ETHREADS) {
        unsigned int c = hcnt[i];
        if (c) {
            atomicAdd(&g_hist_pos[gbase + i], c >> 16);
            atomicAdd(&g_hist_neg[gbase + i], c & 0xFFFFu);
            atomicAdd(&g_hist_sum[gbase + i], hsum[i]);
        }
    }
    // flush edge register accumulators straight to global
    // reduce within warp first to cut atomic count 32x
#pragma unroll
    for (int off = 16; off > 0; off >>= 1) {
        c0 += __shfl_down_sync(0xFFFFFFFFu, c0, off);
        cM += __shfl_down_sync(0xFFFFFFFFu, cM, off);
        s0 += __shfl_down_sync(0xFFFFFFFFu, s0, off);
        sM += __shfl_down_sync(0xFFFFFFFFu, sM, off);
    }
    if ((threadIdx.x & 31) == 0) {
        if (c0) {
            atomicAdd(&g_hist_pos[gbase + 0], c0 >> 16);
            atomicAdd(&g_hist_neg[gbase + 0], c0 & 0xFFFFu);
            atomicAdd(&g_hist_sum[gbase + 0], (unsigned int)s0);
        }
        if (cM) {
            atomicAdd(&g_hist_pos[gbase + NB - 1], cM >> 16);
            atomicAdd(&g_hist_neg[gbase + NB - 1], cM & 0xFFFFu);
            atomicAdd(&g_hist_sum[gbase + NB - 1], (unsigned int)sM);
        }
    }
}

// -------- kernel 4: Lovász via descending-bin scan (parallel over chunks) --------
// Each block handles one 2048-bin chunk of one instance. Its starting (c,k)
// prefix is recomputed by block-reducing the counts of all preceding bins
// (descending order => bins with higher index). No cross-block serialization.
__global__ void k_losshist() {
    int bn = blockIdx.x / LCH;
    int ch = blockIdx.x % LCH;          // chunk index in descending scan order
    float gts = g_cnt[bn];
    size_t gbase = (size_t)bn * NB;

    typedef cub::BlockScan<unsigned long long, LTHREADS> Scan;
    __shared__ typename Scan::TempStorage ts;
    __shared__ unsigned long long wred[8];
    __shared__ unsigned long long s_prefix;

    // ---- prefix: reduce (pos, tot) over bins [NB - ch*LBINS, NB) ----
    unsigned long long acc = 0ull;      // (pos << 32) | tot
    int pre0 = NB - ch * LBINS;
    for (int i = pre0 + (int)threadIdx.x; i < NB; i += LTHREADS) {
        unsigned int p = g_hist_pos[gbase + i];
        unsigned int n = g_hist_neg[gbase + i];
        acc += ((unsigned long long)p << 32) | (unsigned long long)(p + n);
    }
#pragma unroll
    for (int off = 16; off > 0; off >>= 1)
        acc += __shfl_down_sync(0xFFFFFFFFu, acc, off);
    int warp = threadIdx.x >> 5, lane = threadIdx.x & 31;
    if (lane == 0) wred[warp] = acc;
    __syncthreads();
    if (threadIdx.x == 0) {
        unsigned long long s = 0ull;
#pragma unroll
        for (int w = 0; w < LTHREADS / 32; w++) s += wred[w];
        s_prefix = s;
    }
    __syncthreads();
    unsigned long long carry = s_prefix;

    // ---- local chunk: load 2048 bins (descending), one BlockScan ----
    int v0 = ch * LBINS + (int)threadIdx.x * LITEMS;   // descending position of item 0
    unsigned int cp[LITEMS], tot[LITEMS], fx[LITEMS];
    unsigned long long tsum = 0ull;
#pragma unroll
    for (int i = 0; i < LITEMS; i++) {
        int bin = NB - 1 - (v0 + i);
        unsigned int p = g_hist_pos[gbase + bin];
        unsigned int n = g_hist_neg[gbase + bin];
        cp[i] = p; tot[i] = p + n;
        fx[i] = g_hist_sum[gbase + bin];
        tsum += ((unsigned long long)p << 32) | (unsigned long long)(p + n);
    }

    unsigned long long excl;
    Scan(ts).ExclusiveSum(tsum, excl);

    unsigned long long run = carry + excl;
    float loss = 0.f;
#pragma unroll
    for (int i = 0; i < LITEMS; i++) {
        if (tot[i]) {
            float cA = (float)(unsigned int)(run >> 32);
            float kA = (float)(unsigned int)(run & 0xFFFFFFFFull);
            float cBv = cA + (float)cp[i];
            float kBv = kA + (float)tot[i];
            float JA = 1.0f - (gts - cA)  / (gts + kA  - cA);
            float JB = 1.0f - (gts - cBv) / (gts + kBv - cBv);
            float err_rep = (float)fx[i] / (FXS * (float)tot[i]);
            loss += err_rep * (JB - JA);
        }
        run += ((unsigned long long)cp[i] << 32) | (unsigned long long)tot[i];
    }

    // block reduce partial loss (deterministic tree)
    __shared__ float red[LTHREADS];
    red[threadIdx.x] = loss;
    __syncthreads();
    for (int s = LTHREADS / 2; s > 0; s >>= 1) {
        if (threadIdx.x < s) red[threadIdx.x] += red[threadIdx.x + s];
        __syncthreads();
    }
    if (threadIdx.x == 0) g_losspart[blockIdx.x] = red[0];
}

// -------- kernel 5: final deterministic average --------
__global__ void k_final(float* __restrict__ out) {
    if (threadIdx.x == 0) {
        float s = 0.f;
        for (int i = 0; i < BN * LCH; i++) s += g_losspart[i];
        out[0] = s / (float)BN;
    }
}

extern "C" void kernel_launch(void* const* d_in, const int* in_sizes, int n_in,
                              void* d_out, int out_size) {
    const float* f1 = (const float*)d_in[0];
    const float* f2 = (const float*)d_in[1];
    const int*   gt = (const int*)d_in[2];
    float* out = (float*)d_out;

    // zero global histograms
    void *hp = nullptr, *hn = nullptr, *hs = nullptr;
    cudaGetSymbolAddress(&hp, g_hist_pos);
    cudaGetSymbolAddress(&hn, g_hist_neg);
    cudaGetSymbolAddress(&hs, g_hist_sum);
    cudaMemsetAsync(hp, 0, sizeof(unsigned int) * BN * NB);
    cudaMemsetAsync(hn, 0, sizeof(unsigned int) * BN * NB);
    cudaMemsetAsync(hs, 0, sizeof(unsigned int) * BN * NB);

    k_stats<<<BN * SCH, 256>>>(f1, f2, gt);
    k_stats2<<<BN, 64>>>();

    constexpr size_t ESMEM = (size_t)NB * 4 * 2;  // 131072 B
    cudaFuncSetAttribute(k_errhist, cudaFuncAttributeMaxDynamicSharedMemorySize,
                         (int)ESMEM);
    k_errhist<<<BN * ECH, ETHREADS, ESMEM>>>(f1, f2, gt);

    k_losshist<<<BN * LCH, LTHREADS>>>();
    k_final<<<1, 32>>>(out);
}